// round 1
// baseline (speedup 1.0000x reference)
#include <cuda_runtime.h>
#include <cuda_bf16.h>
#include <cstdint>

#define BATCHN 4096
#define SEQLEN 80
#define EMBD   100
#define UNITS  64
#define NG     256                 // 4*UNITS gates
#define MTOT   (BATCHN * SEQLEN)   // 327680 rows

// ---------------- device scratch (allocation-free: device globals) ----------
__device__ float g_Z [(size_t)MTOT * NG];      // 335 MB: gate preactivations (reused for layer 1 & 2)
__device__ float g_h1[(size_t)MTOT * UNITS];   //  84 MB: layer-1 hidden sequence
__device__ float g_h2[BATCHN * UNITS];         //   1 MB: layer-2 last hidden

__device__ __forceinline__ float sigf(float x)  { return 1.0f / (1.0f + __expf(-x)); }
__device__ __forceinline__ float tanhf_(float x){ return 1.0f - 2.0f / (__expf(2.0f * x) + 1.0f); }

// ---------------------------------------------------------------------------
// GEMM: Z[m][0:256] = A[m][0:K] @ W[K][256] + bias
//   GATHER=1: A row m = emb[tokens[m]]  (K=100)
//   GATHER=0: A = g_h1                  (K=64)
// CTA tile 128 rows x 128 cols, 256 threads, thread tile 16x4 (64 FMA : 20 LDS-floats)
// Lane map: tx = tid&31 -> 4 contiguous cols (conflict-free float4 B loads),
//           ty = tid>>5 -> 16 rows (A loads broadcast within warp).
// ---------------------------------------------------------------------------
template<int K, int GATHER>
__global__ void __launch_bounds__(256) gemm_kernel(
    const int*   __restrict__ tokens,
    const float* __restrict__ emb,
    const float* __restrict__ W,
    const float* __restrict__ bias)
{
    extern __shared__ float sm[];
    float* As = sm;            // [K][128] (K-major, transposed tile)
    float* Bs = sm + K * 128;  // [K][128]

    const int m0  = blockIdx.y * 128;
    const int c0  = blockIdx.x * 128;
    const int tid = threadIdx.x;

    if (GATHER) {
        for (int idx = tid; idx < 128 * K; idx += 256) {
            int i = idx / K, k = idx - i * K;
            As[k * 128 + i] = emb[tokens[m0 + i] * K + k];
        }
    } else {
        for (int idx = tid; idx < 128 * K; idx += 256) {
            int i = idx / K, k = idx - i * K;
            As[k * 128 + i] = g_h1[(size_t)(m0 + i) * K + k];
        }
    }
    for (int idx = tid; idx < K * 128; idx += 256) {
        int k = idx >> 7, c = idx & 127;
        Bs[idx] = W[k * NG + c0 + c];
    }
    __syncthreads();

    const int tx = tid & 31;   // col quad
    const int ty = tid >> 5;   // row group of 16

    float acc[16][4];
    #pragma unroll
    for (int i = 0; i < 16; i++) { acc[i][0] = acc[i][1] = acc[i][2] = acc[i][3] = 0.f; }

    #pragma unroll 2
    for (int k = 0; k < K; ++k) {
        float4 b4 = *(const float4*)&Bs[k * 128 + tx * 4];
        float b_[4] = {b4.x, b4.y, b4.z, b4.w};
        #pragma unroll
        for (int ii = 0; ii < 4; ++ii) {
            float4 a4 = *(const float4*)&As[k * 128 + ty * 16 + ii * 4];
            float a_[4] = {a4.x, a4.y, a4.z, a4.w};
            #pragma unroll
            for (int j = 0; j < 4; ++j) {
                #pragma unroll
                for (int c = 0; c < 4; ++c)
                    acc[ii * 4 + j][c] += a_[j] * b_[c];
            }
        }
    }

    float4 bb = *(const float4*)&bias[c0 + tx * 4];
    #pragma unroll
    for (int i = 0; i < 16; ++i) {
        float4 o = make_float4(acc[i][0] + bb.x, acc[i][1] + bb.y,
                               acc[i][2] + bb.z, acc[i][3] + bb.w);
        *(float4*)&g_Z[(size_t)(m0 + ty * 16 + i) * NG + c0 + tx * 4] = o;
    }
}

// ---------------------------------------------------------------------------
// LSTM scan: each CTA owns 16 batch rows for the full 80-step recurrence.
// U (64x256) in SMEM, h (16x64) in SMEM, c in registers (each thread owns
// fixed (row, u) cells across all t -> no c traffic at all).
// 128 threads: q = tid&31 -> u pair (2q, 2q+1); tid>>5 -> 4-row group.
// Thread computes z for 4 rows x 2 u x 4 gates = 32 accumulators.
// Per k: 4 scalar hs loads (warp broadcast) + 4 float2 U loads (contiguous)
//        = 12 floats for 32 FMA.
// ---------------------------------------------------------------------------
template<int STORE_ALL>
__global__ void __launch_bounds__(128) lstm_scan_kernel(const float* __restrict__ U)
{
    extern __shared__ float sm[];
    float* Us = sm;              // [64][256]
    float* hs = sm + 64 * 256;   // [16][64]

    const int tid = threadIdx.x;
    const int b0  = blockIdx.x * 16;

    for (int idx = tid; idx < 64 * 256; idx += 128) Us[idx] = U[idx];
    for (int idx = tid; idx < 16 * 64;  idx += 128) hs[idx] = 0.f;
    __syncthreads();

    const int q  = tid & 31;
    const int u0 = q * 2;
    const int r0 = (tid >> 5) * 4;

    float cc[4][2];
    #pragma unroll
    for (int i = 0; i < 4; i++) { cc[i][0] = 0.f; cc[i][1] = 0.f; }

    for (int t = 0; t < SEQLEN; ++t) {
        float z[4][4][2];
        // init accumulators from precomputed x@W+b (coalesced float2 reads)
        #pragma unroll
        for (int i = 0; i < 4; i++) {
            const float* zr = g_Z + ((size_t)(b0 + r0 + i) * SEQLEN + t) * NG;
            #pragma unroll
            for (int g = 0; g < 4; g++) {
                float2 v = *(const float2*)(zr + g * 64 + u0);
                z[i][g][0] = v.x; z[i][g][1] = v.y;
            }
        }
        // z += h @ U
        #pragma unroll 4
        for (int k = 0; k < 64; ++k) {
            float a0 = hs[(r0 + 0) * 64 + k];
            float a1 = hs[(r0 + 1) * 64 + k];
            float a2 = hs[(r0 + 2) * 64 + k];
            float a3 = hs[(r0 + 3) * 64 + k];
            #pragma unroll
            for (int g = 0; g < 4; g++) {
                float2 w = *(const float2*)(Us + k * NG + g * 64 + u0);
                z[0][g][0] += a0 * w.x; z[0][g][1] += a0 * w.y;
                z[1][g][0] += a1 * w.x; z[1][g][1] += a1 * w.y;
                z[2][g][0] += a2 * w.x; z[2][g][1] += a2 * w.y;
                z[3][g][0] += a3 * w.x; z[3][g][1] += a3 * w.y;
            }
        }
        __syncthreads();   // all reads of h[t-1] done before overwrite
        #pragma unroll
        for (int i = 0; i < 4; i++) {
            float2 hv;
            #pragma unroll
            for (int uu = 0; uu < 2; uu++) {
                float ig = sigf (z[i][0][uu]);
                float fg = sigf (z[i][1][uu]);
                float gg = tanhf_(z[i][2][uu]);
                float og = sigf (z[i][3][uu]);
                float cn = fg * cc[i][uu] + ig * gg;
                cc[i][uu] = cn;
                float h  = og * tanhf_(cn);
                ((float*)&hv)[uu] = h;
            }
            *(float2*)&hs[(r0 + i) * 64 + u0] = hv;
            if (STORE_ALL) {
                *(float2*)&g_h1[((size_t)(b0 + r0 + i) * SEQLEN + t) * UNITS + u0] = hv;
            } else if (t == SEQLEN - 1) {
                *(float2*)&g_h2[(b0 + r0 + i) * UNITS + u0] = hv;
            }
        }
        __syncthreads();   // h[t] visible before next step reads
    }
}

// ---------------------------------------------------------------------------
// Final dense + sigmoid: out[b] = sigmoid(h2_last[b] . Wd + bd)
// ---------------------------------------------------------------------------
__global__ void __launch_bounds__(128) dense_kernel(
    const float* __restrict__ Wd, const float* __restrict__ bd,
    float* __restrict__ out)
{
    __shared__ float wds[64];
    if (threadIdx.x < 64) wds[threadIdx.x] = Wd[threadIdx.x];
    __syncthreads();
    int b = blockIdx.x * blockDim.x + threadIdx.x;
    float s = bd[0];
    const float* h = &g_h2[b * 64];
    #pragma unroll
    for (int u = 0; u < 64; u++) s += h[u] * wds[u];
    out[b] = sigf(s);
}

// ---------------------------------------------------------------------------
extern "C" void kernel_launch(void* const* d_in, const int* in_sizes, int n_in,
                              void* d_out, int out_size)
{
    const int*   tokens = (const int*)  d_in[0];
    const float* emb    = (const float*)d_in[1];
    const float* W1     = (const float*)d_in[2];
    const float* U1     = (const float*)d_in[3];
    const float* b1     = (const float*)d_in[4];
    const float* W2     = (const float*)d_in[5];
    const float* U2     = (const float*)d_in[6];
    const float* b2     = (const float*)d_in[7];
    const float* Wd     = (const float*)d_in[8];
    const float* bd     = (const float*)d_in[9];
    float* out = (float*)d_out;

    const int smem_g1 = 2 * EMBD  * 128 * 4;                 // 102400
    const int smem_g2 = 2 * UNITS * 128 * 4;                 //  65536
    const int smem_s  = (64 * 256 + 16 * 64) * 4;            //  69632

    cudaFuncSetAttribute(gemm_kernel<EMBD, 1>, cudaFuncAttributeMaxDynamicSharedMemorySize, smem_g1);
    cudaFuncSetAttribute(gemm_kernel<UNITS, 0>, cudaFuncAttributeMaxDynamicSharedMemorySize, smem_g2);
    cudaFuncSetAttribute(lstm_scan_kernel<1>, cudaFuncAttributeMaxDynamicSharedMemorySize, smem_s);
    cudaFuncSetAttribute(lstm_scan_kernel<0>, cudaFuncAttributeMaxDynamicSharedMemorySize, smem_s);

    dim3 gemm_grid(NG / 128, MTOT / 128);   // (2, 2560)

    // layer 1: input projection (with embedding gather), then recurrence
    gemm_kernel<EMBD, 1><<<gemm_grid, 256, smem_g1>>>(tokens, emb, W1, b1);
    lstm_scan_kernel<1><<<BATCHN / 16, 128, smem_s>>>(U1);

    // layer 2: input projection from h1 sequence, then recurrence (keep last h only)
    gemm_kernel<UNITS, 0><<<gemm_grid, 256, smem_g2>>>(nullptr, nullptr, W2, b2);
    lstm_scan_kernel<0><<<BATCHN / 16, 128, smem_s>>>(U2);

    // head
    dense_kernel<<<BATCHN / 128, 128>>>(Wd, bd, out);
}

// round 2
// speedup vs baseline: 1.3868x; 1.3868x over previous
#include <cuda_runtime.h>
#include <cuda_bf16.h>
#include <cstdint>

#define BATCHN 4096
#define SEQLEN 80
#define EMBD   100
#define UNITS  64
#define NG     256                 // 4*UNITS gates
#define MTOT   (BATCHN * SEQLEN)   // 327680 rows

typedef unsigned long long u64t;

// ---------------- device scratch (allocation-free: device globals) ----------
__device__ float g_Z [(size_t)MTOT * NG];      // 335 MB gate preactivations
__device__ float g_h1[(size_t)MTOT * UNITS];   //  84 MB layer-1 hidden sequence
__device__ float g_h2[BATCHN * UNITS];         //   1 MB layer-2 last hidden

// ---------------- packed fp32x2 + fast activation helpers -------------------
__device__ __forceinline__ u64t pack2(float x, float y) {
    u64t r; asm("mov.b64 %0, {%1, %2};" : "=l"(r) : "f"(x), "f"(y)); return r;
}
__device__ __forceinline__ void unpack2(u64t v, float& x, float& y) {
    asm("mov.b64 {%0, %1}, %2;" : "=f"(x), "=f"(y) : "l"(v));
}
__device__ __forceinline__ u64t ffma2(u64t a, u64t b, u64t c) {
    u64t d; asm("fma.rn.f32x2 %0, %1, %2, %3;" : "=l"(d) : "l"(a), "l"(b), "l"(c)); return d;
}
__device__ __forceinline__ float tanhapx(float x) {
    float y; asm("tanh.approx.f32 %0, %1;" : "=f"(y) : "f"(x)); return y;
}
__device__ __forceinline__ float sigf(float x) { return fmaf(0.5f, tanhapx(0.5f * x), 0.5f); }

// ---------------------------------------------------------------------------
// GEMM: Z[m][0:256] = A[m][0:K] @ W[K][256] + bias   (f32x2 packed, row pairs)
//   GATHER=1: A row m = emb[tokens[m]]  (K=100);  GATHER=0: A = g_h1 (K=64)
// CTA 128x128, 256 threads, thread tile 16 rows (8 row-pairs) x 4 cols.
// As stored K-major with float2-granular XOR swizzle:
//   A[i][k] -> As[k*128 + (((i>>1) ^ (k&63)) << 1 | (i&1))]
//   - staging stores: 2-way conflict (was 32-way)
//   - compute reads: warp-broadcast LDS.64 row pairs, conflict-free
// ---------------------------------------------------------------------------
template<int K, int GATHER>
__global__ void __launch_bounds__(256, 2) gemm_kernel(
    const int*   __restrict__ tokens,
    const float* __restrict__ emb,
    const float* __restrict__ W,
    const float* __restrict__ bias)
{
    extern __shared__ float sm[];
    float* As = sm;            // swizzled [K][128]
    float* Bs = sm + K * 128;  // [K][128]

    const int m0  = blockIdx.y * 128;
    const int c0  = blockIdx.x * 128;
    const int tid = threadIdx.x;

    for (int idx = tid; idx < 128 * K; idx += 256) {
        int i = idx / K, k = idx - i * K;
        float v = GATHER ? emb[(size_t)tokens[m0 + i] * K + k]
                         : g_h1[(size_t)(m0 + i) * K + k];
        As[k * 128 + ((((i >> 1) ^ (k & 63)) << 1) | (i & 1))] = v;
    }
    for (int idx = tid; idx < K * 128; idx += 256) {
        int k = idx >> 7, c = idx & 127;
        Bs[idx] = W[k * NG + c0 + c];
    }
    __syncthreads();

    const int tx = tid & 31;   // col quad
    const int ty = tid >> 5;   // row-pair group: pairs ty*8 .. ty*8+7

    u64t acc[8][4];
    #pragma unroll
    for (int j = 0; j < 8; j++)
        for (int c = 0; c < 4; c++) acc[j][c] = 0ull;

    #pragma unroll 2
    for (int k = 0; k < K; ++k) {
        float4 b4 = *(const float4*)&Bs[k * 128 + tx * 4];
        u64t pb0 = pack2(b4.x, b4.x), pb1 = pack2(b4.y, b4.y);
        u64t pb2 = pack2(b4.z, b4.z), pb3 = pack2(b4.w, b4.w);
        const float* ak = As + k * 128;
        const int sw = k & 63;
        #pragma unroll
        for (int j = 0; j < 8; j++) {
            u64t a2 = *(const u64t*)(ak + (((ty * 8 + j) ^ sw) << 1));
            acc[j][0] = ffma2(a2, pb0, acc[j][0]);
            acc[j][1] = ffma2(a2, pb1, acc[j][1]);
            acc[j][2] = ffma2(a2, pb2, acc[j][2]);
            acc[j][3] = ffma2(a2, pb3, acc[j][3]);
        }
    }

    float4 bb = *(const float4*)&bias[c0 + tx * 4];
    #pragma unroll
    for (int j = 0; j < 8; j++) {
        float lo0, hi0, lo1, hi1, lo2, hi2, lo3, hi3;
        unpack2(acc[j][0], lo0, hi0);
        unpack2(acc[j][1], lo1, hi1);
        unpack2(acc[j][2], lo2, hi2);
        unpack2(acc[j][3], lo3, hi3);
        const int row = m0 + ty * 16 + 2 * j;
        float4 o0 = make_float4(lo0 + bb.x, lo1 + bb.y, lo2 + bb.z, lo3 + bb.w);
        float4 o1 = make_float4(hi0 + bb.x, hi1 + bb.y, hi2 + bb.z, hi3 + bb.w);
        *(float4*)&g_Z[(size_t)row       * NG + c0 + tx * 4] = o0;
        *(float4*)&g_Z[(size_t)(row + 1) * NG + c0 + tx * 4] = o1;
    }
}

// ---------------------------------------------------------------------------
// LSTM scan: 128 CTAs (one balanced wave), 32 batch rows per CTA, 256 threads.
// U[64][256] in SMEM; h double-buffered in SMEM (one sync/step); c in regs.
// Thread: q=tid&31 -> unit pair u0=2q (f32x2 lanes); (tid>>5)*4 -> 4 rows.
// 16 f32x2 accumulators (4 rows x 4 gates); per k: 4 broadcast h loads +
// 4 LDS.64 U loads + 4 packs + 16 FFMA2.
// Next step's Z row is prefetched into registers to hide DRAM latency.
// ---------------------------------------------------------------------------
template<int STORE_ALL>
__global__ void __launch_bounds__(256, 1) lstm_scan_kernel(const float* __restrict__ U)
{
    extern __shared__ float sm[];
    float* Us = sm;              // [64][256]
    float* hs = sm + 64 * 256;   // [2][32][64]

    const int tid = threadIdx.x;
    const int b0  = blockIdx.x * 32;

    for (int idx = tid; idx < 64 * 256; idx += 256) Us[idx] = U[idx];
    for (int idx = tid; idx < 2 * 32 * 64; idx += 256) hs[idx] = 0.f;
    __syncthreads();

    const int q  = tid & 31;
    const int u0 = q * 2;
    const int r0 = (tid >> 5) * 4;

    float cc[4][2];
    #pragma unroll
    for (int i = 0; i < 4; i++) { cc[i][0] = 0.f; cc[i][1] = 0.f; }

    u64t preZ[4][4];
    #pragma unroll
    for (int i = 0; i < 4; i++) {
        const float* zr = g_Z + ((size_t)(b0 + r0 + i) * SEQLEN) * NG;
        #pragma unroll
        for (int g = 0; g < 4; g++) preZ[i][g] = *(const u64t*)(zr + g * 64 + u0);
    }

    int p = 0;
    for (int t = 0; t < SEQLEN; ++t) {
        u64t z[4][4];
        #pragma unroll
        for (int i = 0; i < 4; i++)
            #pragma unroll
            for (int g = 0; g < 4; g++) z[i][g] = preZ[i][g];

        if (t + 1 < SEQLEN) {
            #pragma unroll
            for (int i = 0; i < 4; i++) {
                const float* zr = g_Z + ((size_t)(b0 + r0 + i) * SEQLEN + t + 1) * NG;
                #pragma unroll
                for (int g = 0; g < 4; g++) preZ[i][g] = *(const u64t*)(zr + g * 64 + u0);
            }
        }

        const float* hb = hs + p * 2048;
        #pragma unroll 4
        for (int k = 0; k < 64; ++k) {
            float a0 = hb[(r0 + 0) * 64 + k];
            float a1 = hb[(r0 + 1) * 64 + k];
            float a2 = hb[(r0 + 2) * 64 + k];
            float a3 = hb[(r0 + 3) * 64 + k];
            u64t p0 = pack2(a0, a0), p1 = pack2(a1, a1);
            u64t p2 = pack2(a2, a2), p3 = pack2(a3, a3);
            const float* uw = Us + k * NG + u0;
            u64t w0 = *(const u64t*)(uw);
            u64t w1 = *(const u64t*)(uw + 64);
            u64t w2 = *(const u64t*)(uw + 128);
            u64t w3 = *(const u64t*)(uw + 192);
            z[0][0] = ffma2(p0, w0, z[0][0]); z[0][1] = ffma2(p0, w1, z[0][1]);
            z[0][2] = ffma2(p0, w2, z[0][2]); z[0][3] = ffma2(p0, w3, z[0][3]);
            z[1][0] = ffma2(p1, w0, z[1][0]); z[1][1] = ffma2(p1, w1, z[1][1]);
            z[1][2] = ffma2(p1, w2, z[1][2]); z[1][3] = ffma2(p1, w3, z[1][3]);
            z[2][0] = ffma2(p2, w0, z[2][0]); z[2][1] = ffma2(p2, w1, z[2][1]);
            z[2][2] = ffma2(p2, w2, z[2][2]); z[2][3] = ffma2(p2, w3, z[2][3]);
            z[3][0] = ffma2(p3, w0, z[3][0]); z[3][1] = ffma2(p3, w1, z[3][1]);
            z[3][2] = ffma2(p3, w2, z[3][2]); z[3][3] = ffma2(p3, w3, z[3][3]);
        }

        float* ho = hs + (p ^ 1) * 2048;
        #pragma unroll
        for (int i = 0; i < 4; i++) {
            float zi0, zi1, zf0, zf1, zg0, zg1, zo0, zo1;
            unpack2(z[i][0], zi0, zi1);
            unpack2(z[i][1], zf0, zf1);
            unpack2(z[i][2], zg0, zg1);
            unpack2(z[i][3], zo0, zo1);
            float h0, h1;
            {
                float ig = sigf(zi0), fg = sigf(zf0), gg = tanhapx(zg0), og = sigf(zo0);
                float cn = fg * cc[i][0] + ig * gg;
                cc[i][0] = cn;
                h0 = og * tanhapx(cn);
            }
            {
                float ig = sigf(zi1), fg = sigf(zf1), gg = tanhapx(zg1), og = sigf(zo1);
                float cn = fg * cc[i][1] + ig * gg;
                cc[i][1] = cn;
                h1 = og * tanhapx(cn);
            }
            u64t hv = pack2(h0, h1);
            *(u64t*)&ho[(r0 + i) * 64 + u0] = hv;
            if (STORE_ALL) {
                *(u64t*)&g_h1[((size_t)(b0 + r0 + i) * SEQLEN + t) * UNITS + u0] = hv;
            } else if (t == SEQLEN - 1) {
                *(u64t*)&g_h2[(size_t)(b0 + r0 + i) * UNITS + u0] = hv;
            }
        }
        __syncthreads();
        p ^= 1;
    }
}

// ---------------------------------------------------------------------------
// Final dense + sigmoid: out[b] = sigmoid(h2_last[b] . Wd + bd)
// ---------------------------------------------------------------------------
__global__ void __launch_bounds__(128) dense_kernel(
    const float* __restrict__ Wd, const float* __restrict__ bd,
    float* __restrict__ out)
{
    __shared__ float wds[64];
    if (threadIdx.x < 64) wds[threadIdx.x] = Wd[threadIdx.x];
    __syncthreads();
    int b = blockIdx.x * blockDim.x + threadIdx.x;
    float s = bd[0];
    const float* h = &g_h2[b * 64];
    #pragma unroll
    for (int u = 0; u < 64; u++) s += h[u] * wds[u];
    out[b] = 1.0f / (1.0f + __expf(-s));
}

// ---------------------------------------------------------------------------
extern "C" void kernel_launch(void* const* d_in, const int* in_sizes, int n_in,
                              void* d_out, int out_size)
{
    const int*   tokens = (const int*)  d_in[0];
    const float* emb    = (const float*)d_in[1];
    const float* W1     = (const float*)d_in[2];
    const float* U1     = (const float*)d_in[3];
    const float* b1     = (const float*)d_in[4];
    const float* W2     = (const float*)d_in[5];
    const float* U2     = (const float*)d_in[6];
    const float* b2     = (const float*)d_in[7];
    const float* Wd     = (const float*)d_in[8];
    const float* bd     = (const float*)d_in[9];
    float* out = (float*)d_out;

    const int smem_g1 = 2 * EMBD  * 128 * 4;                  // 102400
    const int smem_g2 = 2 * UNITS * 128 * 4;                  //  65536
    const int smem_s  = (64 * 256 + 2 * 32 * 64) * 4;         //  81920

    cudaFuncSetAttribute(gemm_kernel<EMBD, 1>,  cudaFuncAttributeMaxDynamicSharedMemorySize, smem_g1);
    cudaFuncSetAttribute(gemm_kernel<UNITS, 0>, cudaFuncAttributeMaxDynamicSharedMemorySize, smem_g2);
    cudaFuncSetAttribute(lstm_scan_kernel<1>,   cudaFuncAttributeMaxDynamicSharedMemorySize, smem_s);
    cudaFuncSetAttribute(lstm_scan_kernel<0>,   cudaFuncAttributeMaxDynamicSharedMemorySize, smem_s);

    dim3 gemm_grid(NG / 128, MTOT / 128);   // (2, 2560)

    // layer 1: input projection (embedding gather) + recurrence
    gemm_kernel<EMBD, 1><<<gemm_grid, 256, smem_g1>>>(tokens, emb, W1, b1);
    lstm_scan_kernel<1><<<BATCHN / 32, 256, smem_s>>>(U1);

    // layer 2: input projection from h1 + recurrence (keep last h only)
    gemm_kernel<UNITS, 0><<<gemm_grid, 256, smem_g2>>>(nullptr, nullptr, W2, b2);
    lstm_scan_kernel<0><<<BATCHN / 32, 256, smem_s>>>(U2);

    // head
    dense_kernel<<<BATCHN / 128, 128>>>(Wd, bd, out);
}

// round 4
// speedup vs baseline: 2.0500x; 1.4782x over previous
#include <cuda_runtime.h>
#include <cuda_bf16.h>
#include <cstdint>

#define BATCHN 4096
#define SEQLEN 80
#define EMBD   100
#define UNITS  64
#define NG     256                 // 4*UNITS gates
#define MTOT   (BATCHN * SEQLEN)   // 327680 rows

typedef unsigned long long u64t;

// ---------------- device scratch (allocation-free: device globals) ----------
__device__ float         g_Z    [(size_t)MTOT * NG];     // 335 MB gate preactivations
__device__ __nv_bfloat16 g_h1bf [(size_t)MTOT * UNITS];  //  42 MB layer-1 hidden (bf16 = GEMM2 A)
__device__ float         g_h2   [BATCHN * UNITS];        //   1 MB layer-2 last hidden
__device__ __nv_bfloat16 g_embbf[10000 * 128];           // 2.5 MB emb->bf16, K zero-padded to 128
__device__ __nv_bfloat16 g_Wt1  [256 * 128];             // W1^T bf16 [n][k], k padded to 128
__device__ __nv_bfloat16 g_Wt2  [256 * 64];              // W2^T bf16 [n][k], k=64

// ---------------- packed fp32x2 + activation helpers ------------------------
__device__ __forceinline__ u64t pack2(float x, float y) {
    u64t r; asm("mov.b64 %0, {%1, %2};" : "=l"(r) : "f"(x), "f"(y)); return r;
}
__device__ __forceinline__ void unpack2(u64t v, float& x, float& y) {
    asm("mov.b64 {%0, %1}, %2;" : "=f"(x), "=f"(y) : "l"(v));
}
__device__ __forceinline__ u64t ffma2(u64t a, u64t b, u64t c) {
    u64t d; asm("fma.rn.f32x2 %0, %1, %2, %3;" : "=l"(d) : "l"(a), "l"(b), "l"(c)); return d;
}
__device__ __forceinline__ float tanhapx(float x) {
    float y; asm("tanh.approx.f32 %0, %1;" : "=f"(y) : "f"(x)); return y;
}
__device__ __forceinline__ float sigf(float x) { return fmaf(0.5f, tanhapx(0.5f * x), 0.5f); }

// bf16 HMMA (sm_80+ portable; NO sm_103a-gated features)
__device__ __forceinline__ void mma16816(float* d, const uint32_t* a, const uint32_t* b) {
    asm volatile(
        "mma.sync.aligned.m16n8k16.row.col.f32.bf16.bf16.f32 "
        "{%0,%1,%2,%3}, {%4,%5,%6,%7}, {%8,%9}, {%0,%1,%2,%3};"
        : "+f"(d[0]), "+f"(d[1]), "+f"(d[2]), "+f"(d[3])
        : "r"(a[0]), "r"(a[1]), "r"(a[2]), "r"(a[3]), "r"(b[0]), "r"(b[1]));
}

// ---------------------------------------------------------------------------
// Pre-conversion kernels (once per launch, ~10 us)
// ---------------------------------------------------------------------------
__global__ void conv_emb_kernel(const float* __restrict__ emb) {
    int idx = blockIdx.x * 256 + threadIdx.x;           // over 10000*128
    int v = idx >> 7, c = idx & 127;
    g_embbf[idx] = (c < EMBD) ? __float2bfloat16(emb[v * EMBD + c]) : __nv_bfloat16(0.f);
}
__global__ void conv_w1_kernel(const float* __restrict__ W) {
    int idx = blockIdx.x * 256 + threadIdx.x;           // over 256*128
    int n = idx >> 7, c = idx & 127;
    g_Wt1[idx] = (c < EMBD) ? __float2bfloat16(W[c * NG + n]) : __nv_bfloat16(0.f);
}
__global__ void conv_w2_kernel(const float* __restrict__ W) {
    int idx = blockIdx.x * 256 + threadIdx.x;           // over 256*64
    int n = idx >> 6, c = idx & 63;
    g_Wt2[idx] = __float2bfloat16(W[c * NG + n]);
}

// ---------------------------------------------------------------------------
// HMMA GEMM: Z[m][0:256] = A[m][0:K] @ W[K][256] + bias   (bf16 in, f32 acc)
// CTA tile 128(m) x 128(n), 8 warps (4 warp-rows x 2 warp-cols), warp tile
// 32x64 = 2 m-tiles x 8 n-tiles of m16n8k16. Fragments loaded with direct
// LDS.32 from row-major SMEM tiles (stride K+8 bf16 -> conflict-free phases).
//   LAYER=1: A row m = g_embbf[tokens[m]] (K=112 incl. zero-pad), W=g_Wt1
//   LAYER=2: A row m = g_h1bf[m]          (K=64),                 W=g_Wt2
// ---------------------------------------------------------------------------
template<int K, int WS, int LAYER>
__global__ void __launch_bounds__(256, 2) gemm_hmma(
    const int* __restrict__ tokens,
    const float* __restrict__ bias)
{
    constexpr int SA = K + 8;           // smem row stride (bf16 elems)
    constexpr int KH = K / 2;           // b32 chunks per row
    extern __shared__ __nv_bfloat16 smbf[];
    __nv_bfloat16* Asm = smbf;          // [128][SA]
    __nv_bfloat16* Bsm = smbf + 128 * SA;

    const __nv_bfloat16* Wt = (LAYER == 1) ? g_Wt1 : g_Wt2;

    const int tid = threadIdx.x;
    const int m0  = blockIdx.y * 128;
    const int c0  = blockIdx.x * 128;

    // stage A (b32 chunks, coalesced per row)
    for (int idx = tid; idx < 128 * KH; idx += 256) {
        int row = idx / KH, kc = (idx - row * KH) * 2;
        uint32_t v;
        if (LAYER == 1) v = *(const uint32_t*)&g_embbf[(size_t)tokens[m0 + row] * 128 + kc];
        else            v = *(const uint32_t*)&g_h1bf[(size_t)(m0 + row) * UNITS + kc];
        *(uint32_t*)&Asm[row * SA + kc] = v;
    }
    // stage B = W^T tile [128 n][K k]
    for (int idx = tid; idx < 128 * KH; idx += 256) {
        int row = idx / KH, kc = (idx - row * KH) * 2;
        *(uint32_t*)&Bsm[row * SA + kc] = *(const uint32_t*)&Wt[(size_t)(c0 + row) * WS + kc];
    }
    __syncthreads();

    const int wid  = tid >> 5, lid = tid & 31;
    const int wrow = wid & 3;           // 4 warp-rows of 32 m
    const int wcol = wid >> 2;          // 2 warp-cols of 64 n
    const int g    = lid >> 2;          // fragment group row / n
    const int t    = lid & 3;           // fragment col pair

    float acc[2][8][4];
    #pragma unroll
    for (int mt = 0; mt < 2; mt++)
        #pragma unroll
        for (int nt = 0; nt < 8; nt++)
            #pragma unroll
            for (int r = 0; r < 4; r++) acc[mt][nt][r] = 0.f;

    #pragma unroll
    for (int s = 0; s < K / 16; s++) {
        const int kk = s * 16 + t * 2;
        uint32_t af[2][4], bf[8][2];
        #pragma unroll
        for (int mt = 0; mt < 2; mt++) {
            const __nv_bfloat16* ab = Asm + (wrow * 32 + mt * 16 + g) * SA + kk;
            af[mt][0] = *(const uint32_t*)(ab);
            af[mt][1] = *(const uint32_t*)(ab + 8 * SA);
            af[mt][2] = *(const uint32_t*)(ab + 8);
            af[mt][3] = *(const uint32_t*)(ab + 8 * SA + 8);
        }
        #pragma unroll
        for (int nt = 0; nt < 8; nt++) {
            const __nv_bfloat16* bb = Bsm + (wcol * 64 + nt * 8 + g) * SA + kk;
            bf[nt][0] = *(const uint32_t*)(bb);
            bf[nt][1] = *(const uint32_t*)(bb + 8);
        }
        #pragma unroll
        for (int mt = 0; mt < 2; mt++)
            #pragma unroll
            for (int nt = 0; nt < 8; nt++)
                mma16816(acc[mt][nt], af[mt], bf[nt]);
    }

    // epilogue: add bias, store float2 per fragment row
    #pragma unroll
    for (int nt = 0; nt < 8; nt++) {
        const int col = c0 + wcol * 64 + nt * 8 + t * 2;
        float2 bb = *(const float2*)&bias[col];
        #pragma unroll
        for (int mt = 0; mt < 2; mt++) {
            const int row = m0 + wrow * 32 + mt * 16 + g;
            float2 o0 = make_float2(acc[mt][nt][0] + bb.x, acc[mt][nt][1] + bb.y);
            float2 o1 = make_float2(acc[mt][nt][2] + bb.x, acc[mt][nt][3] + bb.y);
            *(float2*)&g_Z[(size_t)row * NG + col] = o0;
            *(float2*)&g_Z[(size_t)(row + 8) * NG + col] = o1;
        }
    }
}

// ---------------------------------------------------------------------------
// LSTM scan: 128 CTAs, 32 batch rows per CTA, 256 threads (proven R2 core).
// STORE_ALL=1 -> emit h1 as bf16 (GEMM2 A operand).
// ---------------------------------------------------------------------------
template<int STORE_ALL>
__global__ void __launch_bounds__(256, 1) lstm_scan_kernel(const float* __restrict__ U)
{
    extern __shared__ float sm[];
    float* Us = sm;              // [64][256]
    float* hs = sm + 64 * 256;   // [2][32][64]

    const int tid = threadIdx.x;
    const int b0  = blockIdx.x * 32;

    for (int idx = tid; idx < 64 * 256; idx += 256) Us[idx] = U[idx];
    for (int idx = tid; idx < 2 * 32 * 64; idx += 256) hs[idx] = 0.f;
    __syncthreads();

    const int q  = tid & 31;
    const int u0 = q * 2;
    const int r0 = (tid >> 5) * 4;

    float cc[4][2];
    #pragma unroll
    for (int i = 0; i < 4; i++) { cc[i][0] = 0.f; cc[i][1] = 0.f; }

    u64t preZ[4][4];
    #pragma unroll
    for (int i = 0; i < 4; i++) {
        const float* zr = g_Z + ((size_t)(b0 + r0 + i) * SEQLEN) * NG;
        #pragma unroll
        for (int g = 0; g < 4; g++) preZ[i][g] = *(const u64t*)(zr + g * 64 + u0);
    }

    int p = 0;
    for (int t = 0; t < SEQLEN; ++t) {
        u64t z[4][4];
        #pragma unroll
        for (int i = 0; i < 4; i++)
            #pragma unroll
            for (int g = 0; g < 4; g++) z[i][g] = preZ[i][g];

        if (t + 1 < SEQLEN) {
            #pragma unroll
            for (int i = 0; i < 4; i++) {
                const float* zr = g_Z + ((size_t)(b0 + r0 + i) * SEQLEN + t + 1) * NG;
                #pragma unroll
                for (int g = 0; g < 4; g++) preZ[i][g] = *(const u64t*)(zr + g * 64 + u0);
            }
        }

        const float* hb = hs + p * 2048;
        #pragma unroll 4
        for (int k = 0; k < 64; ++k) {
            float a0 = hb[(r0 + 0) * 64 + k];
            float a1 = hb[(r0 + 1) * 64 + k];
            float a2 = hb[(r0 + 2) * 64 + k];
            float a3 = hb[(r0 + 3) * 64 + k];
            u64t p0 = pack2(a0, a0), p1 = pack2(a1, a1);
            u64t p2 = pack2(a2, a2), p3 = pack2(a3, a3);
            const float* uw = Us + k * NG + u0;
            u64t w0 = *(const u64t*)(uw);
            u64t w1 = *(const u64t*)(uw + 64);
            u64t w2 = *(const u64t*)(uw + 128);
            u64t w3 = *(const u64t*)(uw + 192);
            z[0][0] = ffma2(p0, w0, z[0][0]); z[0][1] = ffma2(p0, w1, z[0][1]);
            z[0][2] = ffma2(p0, w2, z[0][2]); z[0][3] = ffma2(p0, w3, z[0][3]);
            z[1][0] = ffma2(p1, w0, z[1][0]); z[1][1] = ffma2(p1, w1, z[1][1]);
            z[1][2] = ffma2(p1, w2, z[1][2]); z[1][3] = ffma2(p1, w3, z[1][3]);
            z[2][0] = ffma2(p2, w0, z[2][0]); z[2][1] = ffma2(p2, w1, z[2][1]);
            z[2][2] = ffma2(p2, w2, z[2][2]); z[2][3] = ffma2(p2, w3, z[2][3]);
            z[3][0] = ffma2(p3, w0, z[3][0]); z[3][1] = ffma2(p3, w1, z[3][1]);
            z[3][2] = ffma2(p3, w2, z[3][2]); z[3][3] = ffma2(p3, w3, z[3][3]);
        }

        float* ho = hs + (p ^ 1) * 2048;
        #pragma unroll
        for (int i = 0; i < 4; i++) {
            float zi0, zi1, zf0, zf1, zg0, zg1, zo0, zo1;
            unpack2(z[i][0], zi0, zi1);
            unpack2(z[i][1], zf0, zf1);
            unpack2(z[i][2], zg0, zg1);
            unpack2(z[i][3], zo0, zo1);
            float h0, h1;
            {
                float ig = sigf(zi0), fg = sigf(zf0), gg = tanhapx(zg0), og = sigf(zo0);
                float cn = fg * cc[i][0] + ig * gg;
                cc[i][0] = cn;
                h0 = og * tanhapx(cn);
            }
            {
                float ig = sigf(zi1), fg = sigf(zf1), gg = tanhapx(zg1), og = sigf(zo1);
                float cn = fg * cc[i][1] + ig * gg;
                cc[i][1] = cn;
                h1 = og * tanhapx(cn);
            }
            *(u64t*)&ho[(r0 + i) * 64 + u0] = pack2(h0, h1);
            if (STORE_ALL) {
                __nv_bfloat162 hv2 = __float22bfloat162_rn(make_float2(h0, h1));
                *(__nv_bfloat162*)&g_h1bf[((size_t)(b0 + r0 + i) * SEQLEN + t) * UNITS + u0] = hv2;
            } else if (t == SEQLEN - 1) {
                *(float2*)&g_h2[(size_t)(b0 + r0 + i) * UNITS + u0] = make_float2(h0, h1);
            }
        }
        __syncthreads();
        p ^= 1;
    }
}

// ---------------------------------------------------------------------------
// Final dense + sigmoid
// ---------------------------------------------------------------------------
__global__ void __launch_bounds__(128) dense_kernel(
    const float* __restrict__ Wd, const float* __restrict__ bd,
    float* __restrict__ out)
{
    __shared__ float wds[64];
    if (threadIdx.x < 64) wds[threadIdx.x] = Wd[threadIdx.x];
    __syncthreads();
    int b = blockIdx.x * blockDim.x + threadIdx.x;
    float s = bd[0];
    const float* h = &g_h2[b * 64];
    #pragma unroll
    for (int u = 0; u < 64; u++) s += h[u] * wds[u];
    out[b] = 1.0f / (1.0f + __expf(-s));
}

// ---------------------------------------------------------------------------
extern "C" void kernel_launch(void* const* d_in, const int* in_sizes, int n_in,
                              void* d_out, int out_size)
{
    const int*   tokens = (const int*)  d_in[0];
    const float* emb    = (const float*)d_in[1];
    const float* W1     = (const float*)d_in[2];
    const float* U1     = (const float*)d_in[3];
    const float* b1     = (const float*)d_in[4];
    const float* W2     = (const float*)d_in[5];
    const float* U2     = (const float*)d_in[6];
    const float* b2     = (const float*)d_in[7];
    const float* Wd     = (const float*)d_in[8];
    const float* bd     = (const float*)d_in[9];
    float* out = (float*)d_out;

    const int smem_g1 = 2 * 128 * (112 + 8) * 2;       // 61440
    const int smem_g2 = 2 * 128 * (64 + 8) * 2;        // 36864
    const int smem_s  = (64 * 256 + 2 * 32 * 64) * 4;  // 81920

    cudaFuncSetAttribute(gemm_hmma<112, 128, 1>, cudaFuncAttributeMaxDynamicSharedMemorySize, smem_g1);
    cudaFuncSetAttribute(gemm_hmma<64, 64, 2>,   cudaFuncAttributeMaxDynamicSharedMemorySize, smem_g2);
    cudaFuncSetAttribute(lstm_scan_kernel<1>,    cudaFuncAttributeMaxDynamicSharedMemorySize, smem_s);
    cudaFuncSetAttribute(lstm_scan_kernel<0>,    cudaFuncAttributeMaxDynamicSharedMemorySize, smem_s);

    // one-time bf16 conversions (zero-padded where needed)
    conv_emb_kernel<<<10000 * 128 / 256, 256>>>(emb);
    conv_w1_kernel<<<256 * 128 / 256, 256>>>(W1);
    conv_w2_kernel<<<256 * 64 / 256, 256>>>(W2);

    dim3 ggrid(2, MTOT / 128);   // (n-halves, m-tiles)

    // layer 1: HMMA input projection (gathered emb) + recurrence (emits h1 bf16)
    gemm_hmma<112, 128, 1><<<ggrid, 256, smem_g1>>>(tokens, b1);
    lstm_scan_kernel<1><<<BATCHN / 32, 256, smem_s>>>(U1);

    // layer 2: HMMA input projection + recurrence (keep last h only)
    gemm_hmma<64, 64, 2><<<ggrid, 256, smem_g2>>>(nullptr, b2);
    lstm_scan_kernel<0><<<BATCHN / 32, 256, smem_s>>>(U2);

    // head
    dense_kernel<<<BATCHN / 128, 128>>>(Wd, bd, out);
}

// round 5
// speedup vs baseline: 3.1603x; 1.5416x over previous
#include <cuda_runtime.h>
#include <cuda_bf16.h>
#include <cstdint>

#define BATCHN 4096
#define SEQLEN 80
#define EMBD   100
#define UNITS  64
#define NG     256                 // 4*UNITS gates
#define MTOT   (BATCHN * SEQLEN)   // 327680 rows

typedef unsigned long long u64t;

// ---------------- device scratch (allocation-free: device globals) ----------
__device__ float         g_Z    [(size_t)MTOT * NG];     // 335 MB gate preactivations
__device__ __nv_bfloat16 g_h1bf [(size_t)MTOT * UNITS];  //  42 MB layer-1 hidden (bf16 = GEMM2 A)
__device__ float         g_h2   [BATCHN * UNITS];        //   1 MB layer-2 last hidden
__device__ __nv_bfloat16 g_embbf[10000 * 128];           // 2.5 MB emb->bf16, K zero-padded to 128
__device__ __nv_bfloat16 g_Wt1  [256 * 128];             // W1^T bf16 [n][k], k padded to 128
__device__ __nv_bfloat16 g_Wt2  [256 * 64];              // W2^T bf16 [n][k], k=64

// ---------------- helpers ---------------------------------------------------
__device__ __forceinline__ float tanhapx(float x) {
    float y; asm("tanh.approx.f32 %0, %1;" : "=f"(y) : "f"(x)); return y;
}
__device__ __forceinline__ float sigf(float x) { return fmaf(0.5f, tanhapx(0.5f * x), 0.5f); }

__device__ __forceinline__ uint32_t smem_u32(const void* p) {
    uint32_t a;
    asm("{ .reg .u64 t; cvta.to.shared.u64 t, %1; cvt.u32.u64 %0, t; }" : "=r"(a) : "l"(p));
    return a;
}
__device__ __forceinline__ uint32_t packbf(float x, float y) {
    __nv_bfloat162 v = __float22bfloat162_rn(make_float2(x, y));
    return *(uint32_t*)&v;
}
// bf16 HMMA m16n8k16 (sm_80+ portable)
__device__ __forceinline__ void mma16816(float* d, const uint32_t* a, const uint32_t* b) {
    asm volatile(
        "mma.sync.aligned.m16n8k16.row.col.f32.bf16.bf16.f32 "
        "{%0,%1,%2,%3}, {%4,%5,%6,%7}, {%8,%9}, {%0,%1,%2,%3};"
        : "+f"(d[0]), "+f"(d[1]), "+f"(d[2]), "+f"(d[3])
        : "r"(a[0]), "r"(a[1]), "r"(a[2]), "r"(a[3]), "r"(b[0]), "r"(b[1]));
}
__device__ __forceinline__ void ldmx4(uint32_t* r, uint32_t addr) {
    asm volatile("ldmatrix.sync.aligned.m8n8.x4.shared.b16 {%0,%1,%2,%3}, [%4];"
        : "=r"(r[0]), "=r"(r[1]), "=r"(r[2]), "=r"(r[3]) : "r"(addr));
}

// ---------------------------------------------------------------------------
// Pre-conversion kernels (once per launch)
// ---------------------------------------------------------------------------
__global__ void conv_emb_kernel(const float* __restrict__ emb) {
    int idx = blockIdx.x * 256 + threadIdx.x;           // over 10000*128
    int v = idx >> 7, c = idx & 127;
    g_embbf[idx] = (c < EMBD) ? __float2bfloat16(emb[v * EMBD + c]) : __nv_bfloat16(0.f);
}
__global__ void conv_w1_kernel(const float* __restrict__ W) {
    int idx = blockIdx.x * 256 + threadIdx.x;           // over 256*128
    int n = idx >> 7, c = idx & 127;
    g_Wt1[idx] = (c < EMBD) ? __float2bfloat16(W[c * NG + n]) : __nv_bfloat16(0.f);
}
__global__ void conv_w2_kernel(const float* __restrict__ W) {
    int idx = blockIdx.x * 256 + threadIdx.x;           // over 256*64
    int n = idx >> 6, c = idx & 63;
    g_Wt2[idx] = __float2bfloat16(W[c * NG + n]);
}

// ---------------------------------------------------------------------------
// HMMA GEMM: Z[m][0:256] = A[m][0:K] @ W[K][256] + bias   (bf16 in, f32 acc)
// CTA 128x128, 8 warps (4 wrow x 2 wcol), warp tile 32x64. Fragment loads via
// ldmatrix.x4 (row stride K+8 -> 16B-aligned, bank-conflict-free).
// ---------------------------------------------------------------------------
template<int K, int WS, int LAYER>
__global__ void __launch_bounds__(256, 2) gemm_hmma(
    const int* __restrict__ tokens,
    const float* __restrict__ bias)
{
    constexpr int SA = K + 8;           // smem row stride (bf16 elems); (K+8)*2 % 16 == 0
    constexpr int KH = K / 2;           // b32 chunks per row
    extern __shared__ __nv_bfloat16 smbf[];
    __nv_bfloat16* Asm = smbf;          // [128][SA]
    __nv_bfloat16* Bsm = smbf + 128 * SA;

    const __nv_bfloat16* Wt = (LAYER == 1) ? g_Wt1 : g_Wt2;

    const int tid = threadIdx.x;
    const int m0  = blockIdx.y * 128;
    const int c0  = blockIdx.x * 128;

    for (int idx = tid; idx < 128 * KH; idx += 256) {
        int row = idx / KH, kc = (idx - row * KH) * 2;
        uint32_t v;
        if (LAYER == 1) v = *(const uint32_t*)&g_embbf[(size_t)tokens[m0 + row] * 128 + kc];
        else            v = *(const uint32_t*)&g_h1bf[(size_t)(m0 + row) * UNITS + kc];
        *(uint32_t*)&Asm[row * SA + kc] = v;
    }
    for (int idx = tid; idx < 128 * KH; idx += 256) {
        int row = idx / KH, kc = (idx - row * KH) * 2;
        *(uint32_t*)&Bsm[row * SA + kc] = *(const uint32_t*)&Wt[(size_t)(c0 + row) * WS + kc];
    }
    __syncthreads();

    const int wid  = tid >> 5, lid = tid & 31;
    const int wrow = wid & 3;           // 4 warp-rows of 32 m
    const int wcol = wid >> 2;          // 2 warp-cols of 64 n
    const int g    = lid >> 2;
    const int t    = lid & 3;

    const uint32_t a_base = smem_u32(Asm);
    const uint32_t b_base = smem_u32(Bsm);
    // A ldmatrix lane address pieces
    const uint32_t a_lane = (uint32_t)((wrow * 32 + (lid & 15)) * SA * 2 + (lid >> 4) * 16);
    // B ldmatrix lane address pieces: n = wcol*64 + np*16 + (lid>>4)*8 + (lid&7); koff = ((lid>>3)&1)*8
    const uint32_t b_lane = (uint32_t)((wcol * 64 + (lid >> 4) * 8 + (lid & 7)) * SA * 2 +
                                       ((lid >> 3) & 1) * 16);

    float acc[2][8][4];
    #pragma unroll
    for (int mt = 0; mt < 2; mt++)
        #pragma unroll
        for (int nt = 0; nt < 8; nt++)
            #pragma unroll
            for (int r = 0; r < 4; r++) acc[mt][nt][r] = 0.f;

    #pragma unroll
    for (int s = 0; s < K / 16; s++) {
        uint32_t af[2][4], bfr[8][2];
        #pragma unroll
        for (int mt = 0; mt < 2; mt++)
            ldmx4(af[mt], a_base + a_lane + (uint32_t)(mt * 16 * SA * 2 + s * 32));
        #pragma unroll
        for (int np = 0; np < 4; np++) {
            uint32_t bq[4];
            ldmx4(bq, b_base + b_lane + (uint32_t)(np * 16 * SA * 2 + s * 32));
            bfr[np * 2][0] = bq[0]; bfr[np * 2][1] = bq[1];
            bfr[np * 2 + 1][0] = bq[2]; bfr[np * 2 + 1][1] = bq[3];
        }
        #pragma unroll
        for (int mt = 0; mt < 2; mt++)
            #pragma unroll
            for (int nt = 0; nt < 8; nt++)
                mma16816(acc[mt][nt], af[mt], bfr[nt]);
    }

    #pragma unroll
    for (int nt = 0; nt < 8; nt++) {
        const int col = c0 + wcol * 64 + nt * 8 + t * 2;
        float2 bb = *(const float2*)&bias[col];
        #pragma unroll
        for (int mt = 0; mt < 2; mt++) {
            const int row = m0 + wrow * 32 + mt * 16 + g;
            *(float2*)&g_Z[(size_t)row * NG + col] =
                make_float2(acc[mt][nt][0] + bb.x, acc[mt][nt][1] + bb.y);
            *(float2*)&g_Z[(size_t)(row + 8) * NG + col] =
                make_float2(acc[mt][nt][2] + bb.x, acc[mt][nt][3] + bb.y);
        }
    }
}

// ---------------------------------------------------------------------------
// Tensor-core LSTM scan: 128 CTAs, 32 batch rows/CTA, 256 threads (8 warps).
// U held in registers as B fragments (per warp: same 8 units across all 4
// gates -> each thread owns complete i/f/g/o quadruples, c stays in regs).
// Per step: Z(t) prefetched into regs a step ahead; h(t-1) read from SMEM via
// ldmatrix.x4 (stride 72 bf16 = 144B, conflict-free); 32 mma/warp; gates;
// h(t) written bf16 to the other SMEM buffer; one __syncthreads per step.
// ---------------------------------------------------------------------------
template<int STORE_ALL>
__global__ void __launch_bounds__(256, 1) lstm_scan_mma(const float* __restrict__ U)
{
    __align__(16) __shared__ __nv_bfloat16 hsm[2][32][72];   // 2 x 32 x 72 bf16

    const int tid = threadIdx.x, wid = tid >> 5, lid = tid & 31;
    const int g = lid >> 2, t4 = lid & 3;
    const int b0 = blockIdx.x * 32;

    {   // zero both h buffers
        uint32_t* hz = (uint32_t*)&hsm[0][0][0];
        for (int i = tid; i < 2 * 32 * 72 / 2; i += 256) hz[i] = 0u;
    }

    // B fragments of U: [gate][ktile][2]
    uint32_t bfr[4][4][2];
    #pragma unroll
    for (int gg = 0; gg < 4; gg++) {
        const int n = gg * 64 + wid * 8 + g;
        #pragma unroll
        for (int kt = 0; kt < 4; kt++) {
            const int k0 = kt * 16 + t4 * 2;
            bfr[gg][kt][0] = packbf(U[(size_t)k0 * NG + n],       U[(size_t)(k0 + 1) * NG + n]);
            bfr[gg][kt][1] = packbf(U[(size_t)(k0 + 8) * NG + n], U[(size_t)(k0 + 9) * NG + n]);
        }
    }

    // ldmatrix lane offset within an h buffer
    const uint32_t h0_base = smem_u32(&hsm[0][0][0]);
    const uint32_t h1_base = smem_u32(&hsm[1][0][0]);
    const uint32_t a_lane  = (uint32_t)((lid & 15) * 144 + (lid >> 4) * 16);

    float cst[2][2][2];
    #pragma unroll
    for (int mt = 0; mt < 2; mt++)
        for (int rs = 0; rs < 2; rs++)
            for (int uu = 0; uu < 2; uu++) cst[mt][rs][uu] = 0.f;

    // prefetch Z(0)
    float zpre[2][4][4];
    #pragma unroll
    for (int mt = 0; mt < 2; mt++)
        #pragma unroll
        for (int gg = 0; gg < 4; gg++) {
            const int col = gg * 64 + wid * 8 + t4 * 2;
            float2 a = *(const float2*)&g_Z[((size_t)(b0 + mt * 16 + g) * SEQLEN) * NG + col];
            float2 b = *(const float2*)&g_Z[((size_t)(b0 + mt * 16 + g + 8) * SEQLEN) * NG + col];
            zpre[mt][gg][0] = a.x; zpre[mt][gg][1] = a.y;
            zpre[mt][gg][2] = b.x; zpre[mt][gg][3] = b.y;
        }
    __syncthreads();

    int p = 0;
    for (int t = 0; t < SEQLEN; ++t) {
        // acc = Z(t)
        float acc[2][4][4];
        #pragma unroll
        for (int mt = 0; mt < 2; mt++)
            #pragma unroll
            for (int gg = 0; gg < 4; gg++)
                #pragma unroll
                for (int r = 0; r < 4; r++) acc[mt][gg][r] = zpre[mt][gg][r];

        // prefetch Z(t+1)
        if (t + 1 < SEQLEN) {
            #pragma unroll
            for (int mt = 0; mt < 2; mt++)
                #pragma unroll
                for (int gg = 0; gg < 4; gg++) {
                    const int col = gg * 64 + wid * 8 + t4 * 2;
                    float2 a = *(const float2*)&g_Z[((size_t)(b0 + mt * 16 + g) * SEQLEN + t + 1) * NG + col];
                    float2 b = *(const float2*)&g_Z[((size_t)(b0 + mt * 16 + g + 8) * SEQLEN + t + 1) * NG + col];
                    zpre[mt][gg][0] = a.x; zpre[mt][gg][1] = a.y;
                    zpre[mt][gg][2] = b.x; zpre[mt][gg][3] = b.y;
                }
        }

        // A fragments of h(t-1)
        const uint32_t hb = p ? h1_base : h0_base;
        uint32_t af[2][4][4];
        #pragma unroll
        for (int mt = 0; mt < 2; mt++)
            #pragma unroll
            for (int kt = 0; kt < 4; kt++)
                ldmx4(af[mt][kt], hb + a_lane + (uint32_t)(mt * 16 * 144 + kt * 32));

        // z += h @ U
        #pragma unroll
        for (int mt = 0; mt < 2; mt++)
            #pragma unroll
            for (int gg = 0; gg < 4; gg++)
                #pragma unroll
                for (int kt = 0; kt < 4; kt++)
                    mma16816(acc[mt][gg], af[mt][kt], bfr[gg][kt]);

        // gates + state update + h write
        #pragma unroll
        for (int mt = 0; mt < 2; mt++)
            #pragma unroll
            for (int rs = 0; rs < 2; rs++) {
                const int row = mt * 16 + g + rs * 8;
                float hv0, hv1;
                {
                    float zi = acc[mt][0][rs * 2], zf = acc[mt][1][rs * 2];
                    float zg = acc[mt][2][rs * 2], zo = acc[mt][3][rs * 2];
                    float cn = sigf(zf) * cst[mt][rs][0] + sigf(zi) * tanhapx(zg);
                    cst[mt][rs][0] = cn;
                    hv0 = sigf(zo) * tanhapx(cn);
                }
                {
                    float zi = acc[mt][0][rs * 2 + 1], zf = acc[mt][1][rs * 2 + 1];
                    float zg = acc[mt][2][rs * 2 + 1], zo = acc[mt][3][rs * 2 + 1];
                    float cn = sigf(zf) * cst[mt][rs][1] + sigf(zi) * tanhapx(zg);
                    cst[mt][rs][1] = cn;
                    hv1 = sigf(zo) * tanhapx(cn);
                }
                __nv_bfloat162 h2 = __float22bfloat162_rn(make_float2(hv0, hv1));
                *(__nv_bfloat162*)&hsm[p ^ 1][row][wid * 8 + t4 * 2] = h2;
                if (STORE_ALL) {
                    *(__nv_bfloat162*)&g_h1bf[((size_t)(b0 + row) * SEQLEN + t) * UNITS + wid * 8 + t4 * 2] = h2;
                } else if (t == SEQLEN - 1) {
                    *(float2*)&g_h2[(size_t)(b0 + row) * UNITS + wid * 8 + t4 * 2] = make_float2(hv0, hv1);
                }
            }
        __syncthreads();
        p ^= 1;
    }
}

// ---------------------------------------------------------------------------
// Final dense + sigmoid
// ---------------------------------------------------------------------------
__global__ void __launch_bounds__(128) dense_kernel(
    const float* __restrict__ Wd, const float* __restrict__ bd,
    float* __restrict__ out)
{
    __shared__ float wds[64];
    if (threadIdx.x < 64) wds[threadIdx.x] = Wd[threadIdx.x];
    __syncthreads();
    int b = blockIdx.x * blockDim.x + threadIdx.x;
    float s = bd[0];
    const float* h = &g_h2[b * 64];
    #pragma unroll
    for (int u = 0; u < 64; u++) s += h[u] * wds[u];
    out[b] = 1.0f / (1.0f + __expf(-s));
}

// ---------------------------------------------------------------------------
extern "C" void kernel_launch(void* const* d_in, const int* in_sizes, int n_in,
                              void* d_out, int out_size)
{
    const int*   tokens = (const int*)  d_in[0];
    const float* emb    = (const float*)d_in[1];
    const float* W1     = (const float*)d_in[2];
    const float* U1     = (const float*)d_in[3];
    const float* b1     = (const float*)d_in[4];
    const float* W2     = (const float*)d_in[5];
    const float* U2     = (const float*)d_in[6];
    const float* b2     = (const float*)d_in[7];
    const float* Wd     = (const float*)d_in[8];
    const float* bd     = (const float*)d_in[9];
    float* out = (float*)d_out;

    const int smem_g1 = 2 * 128 * (112 + 8) * 2;       // 61440
    const int smem_g2 = 2 * 128 * (64 + 8) * 2;        // 36864

    cudaFuncSetAttribute(gemm_hmma<112, 128, 1>, cudaFuncAttributeMaxDynamicSharedMemorySize, smem_g1);
    cudaFuncSetAttribute(gemm_hmma<64, 64, 2>,   cudaFuncAttributeMaxDynamicSharedMemorySize, smem_g2);

    // one-time bf16 conversions (zero-padded where needed)
    conv_emb_kernel<<<10000 * 128 / 256, 256>>>(emb);
    conv_w1_kernel<<<256 * 128 / 256, 256>>>(W1);
    conv_w2_kernel<<<256 * 64 / 256, 256>>>(W2);

    dim3 ggrid(2, MTOT / 128);   // (n-halves, m-tiles)

    // layer 1: HMMA input projection (gathered emb) + tensor-core recurrence
    gemm_hmma<112, 128, 1><<<ggrid, 256, smem_g1>>>(tokens, b1);
    lstm_scan_mma<1><<<BATCHN / 32, 256>>>(U1);

    // layer 2: HMMA input projection + tensor-core recurrence (last h only)
    gemm_hmma<64, 64, 2><<<ggrid, 256, smem_g2>>>(nullptr, b2);
    lstm_scan_mma<0><<<BATCHN / 32, 256>>>(U2);

    // head
    dense_kernel<<<BATCHN / 128, 128>>>(Wd, bd, out);
}

// round 6
// speedup vs baseline: 10.5118x; 3.3262x over previous
#include <cuda_runtime.h>
#include <cuda_bf16.h>
#include <cstdint>

#define BATCHN 4096
#define SEQLEN 80
#define EMBD   100
#define UNITS  64
#define NG     256                 // 4*UNITS gates
#define MTOT   (BATCHN * SEQLEN)

typedef unsigned long long u64t;

// ---------------- device scratch (allocation-free: device globals) ----------
__device__ __nv_bfloat16 g_h1bf [(size_t)MTOT * UNITS];  // 42 MB layer-1 hidden seq (bf16)
__device__ float         g_h2   [BATCHN * UNITS];        //  1 MB layer-2 last hidden
__device__ __nv_bfloat16 g_embbf[10000 * 128];           // 2.5 MB emb->bf16, K padded to 128
__device__ __nv_bfloat16 g_Wt1  [256 * 128];             // W1^T bf16 [n][k], k padded to 128
__device__ __nv_bfloat16 g_Wt2  [256 * 64];              // W2^T bf16 [n][k], k=64

// ---------------- helpers ---------------------------------------------------
__device__ __forceinline__ float tanhapx(float x) {
    float y; asm("tanh.approx.f32 %0, %1;" : "=f"(y) : "f"(x)); return y;
}
__device__ __forceinline__ float sigf(float x) { return fmaf(0.5f, tanhapx(0.5f * x), 0.5f); }

__device__ __forceinline__ uint32_t smem_u32(const void* p) {
    uint32_t a;
    asm("{ .reg .u64 t; cvta.to.shared.u64 t, %1; cvt.u32.u64 %0, t; }" : "=r"(a) : "l"(p));
    return a;
}
__device__ __forceinline__ uint32_t packbf(float x, float y) {
    __nv_bfloat162 v = __float22bfloat162_rn(make_float2(x, y));
    return *(uint32_t*)&v;
}
__device__ __forceinline__ void mma16816(float* d, const uint32_t* a, const uint32_t* b) {
    asm volatile(
        "mma.sync.aligned.m16n8k16.row.col.f32.bf16.bf16.f32 "
        "{%0,%1,%2,%3}, {%4,%5,%6,%7}, {%8,%9}, {%0,%1,%2,%3};"
        : "+f"(d[0]), "+f"(d[1]), "+f"(d[2]), "+f"(d[3])
        : "r"(a[0]), "r"(a[1]), "r"(a[2]), "r"(a[3]), "r"(b[0]), "r"(b[1]));
}
__device__ __forceinline__ void ldmx4(uint32_t* r, uint32_t addr) {
    asm volatile("ldmatrix.sync.aligned.m8n8.x4.shared.b16 {%0,%1,%2,%3}, [%4];"
        : "=r"(r[0]), "=r"(r[1]), "=r"(r[2]), "=r"(r[3]) : "r"(addr));
}
__device__ __forceinline__ void cpa16(uint32_t dst, const void* gsrc) {
    asm volatile("{ .reg .u64 ga; cvta.to.global.u64 ga, %1; "
                 "cp.async.ca.shared.global [%0], [ga], 16; }"
                 :: "r"(dst), "l"(gsrc) : "memory");
}
#define CPA_COMMIT() asm volatile("cp.async.commit_group;" ::: "memory")
#define CPA_WAIT0()  asm volatile("cp.async.wait_group 0;" ::: "memory")

// ---------------------------------------------------------------------------
// Pre-conversion kernels (once per launch)
// ---------------------------------------------------------------------------
__global__ void conv_emb_kernel(const float* __restrict__ emb) {
    int idx = blockIdx.x * 256 + threadIdx.x;           // over 10000*128
    int v = idx >> 7, c = idx & 127;
    g_embbf[idx] = (c < EMBD) ? __float2bfloat16(emb[v * EMBD + c]) : __nv_bfloat16(0.f);
}
__global__ void conv_w1_kernel(const float* __restrict__ W) {
    int idx = blockIdx.x * 256 + threadIdx.x;           // over 256*128
    int n = idx >> 7, c = idx & 127;
    g_Wt1[idx] = (c < EMBD) ? __float2bfloat16(W[c * NG + n]) : __nv_bfloat16(0.f);
}
__global__ void conv_w2_kernel(const float* __restrict__ W) {
    int idx = blockIdx.x * 256 + threadIdx.x;           // over 256*64
    int n = idx >> 6, c = idx & 63;
    g_Wt2[idx] = __float2bfloat16(W[c * NG + n]);
}

// ---------------------------------------------------------------------------
// Fully fused LSTM layer: per CTA 32 batch rows, 80 steps, 256 threads.
//  z(t) = x(t)@W + h(t-1)@U + b computed entirely on tensor cores:
//   - x(t) tile (32 x KX bf16) staged via cp.async, double-buffered, one step
//     ahead (LAYER=1: gather emb rows by token; LAYER=2: stream g_h1bf)
//   - W, U held in registers as B fragments (loaded once)
//   - h double-buffered in SMEM, ldmatrix A fragments; c in registers
//  Warp owns units n = gate*64 + wid*8 + g  -> each thread holds complete
//  (i,f,g,o) quadruples for its cells; one __syncthreads per step.
// ---------------------------------------------------------------------------
template<int KX, int LAYER>
__global__ void __launch_bounds__(256, 1) lstm_fused(
    const int*   __restrict__ tokens,
    const float* __restrict__ U,
    const float* __restrict__ bias)
{
    constexpr int KXP = KX + 8;            // x row stride (bf16): 120 / 72 -> conflict-free
    constexpr int NKT = KX / 16;           // x k-tiles: 7 / 4
    constexpr int NCH = KX / 8;            // 16B chunks per x row: 14 / 8

    __shared__ __nv_bfloat16 xs[2][32][KXP];
    __shared__ __nv_bfloat16 hsm[2][32][72];
    __shared__ int toks[(LAYER == 1) ? 32 * SEQLEN : 8];

    const int tid = threadIdx.x, wid = tid >> 5, lid = tid & 31;
    const int g = lid >> 2, t4 = lid & 3;
    const int b0 = blockIdx.x * 32;

    {   // zero h buffers
        uint32_t* hz = (uint32_t*)&hsm[0][0][0];
        for (int i = tid; i < 2 * 32 * 72 / 2; i += 256) hz[i] = 0u;
    }
    if (LAYER == 1) {
        for (int idx = tid; idx < 32 * SEQLEN; idx += 256)
            toks[idx] = tokens[(size_t)(b0 + idx / SEQLEN) * SEQLEN + idx % SEQLEN];
    }

    // ---- B fragments: W (bf16 pre-transposed) and U (packed from f32) ----
    const __nv_bfloat16* Wt = (LAYER == 1) ? g_Wt1 : g_Wt2;
    constexpr int WSTR = (LAYER == 1) ? 128 : 64;
    uint32_t bw[4][NKT][2], bu[4][4][2];
    float bx[4][2];
    #pragma unroll
    for (int gg = 0; gg < 4; gg++) {
        const int n = gg * 64 + wid * 8 + g;
        #pragma unroll
        for (int kt = 0; kt < NKT; kt++) {
            const __nv_bfloat16* wb = Wt + (size_t)n * WSTR + kt * 16 + t4 * 2;
            bw[gg][kt][0] = *(const uint32_t*)wb;
            bw[gg][kt][1] = *(const uint32_t*)(wb + 8);
        }
        #pragma unroll
        for (int kt = 0; kt < 4; kt++) {
            const int k0 = kt * 16 + t4 * 2;
            bu[gg][kt][0] = packbf(U[(size_t)k0 * NG + n],       U[(size_t)(k0 + 1) * NG + n]);
            bu[gg][kt][1] = packbf(U[(size_t)(k0 + 8) * NG + n], U[(size_t)(k0 + 9) * NG + n]);
        }
        const int col = gg * 64 + wid * 8 + t4 * 2;
        bx[gg][0] = bias[col]; bx[gg][1] = bias[col + 1];
    }
    __syncthreads();   // toks + zeroed h visible

    const uint32_t xs0 = smem_u32(&xs[0][0][0]);
    const uint32_t xs1 = smem_u32(&xs[1][0][0]);
    const uint32_t h0b = smem_u32(&hsm[0][0][0]);
    const uint32_t h1b = smem_u32(&hsm[1][0][0]);
    const uint32_t a_lane_x = (uint32_t)((lid & 15) * (KXP * 2) + (lid >> 4) * 16);
    const uint32_t a_lane_h = (uint32_t)((lid & 15) * 144 + (lid >> 4) * 16);

    auto stage_x = [&](int buf, int t) {
        const uint32_t dbase = buf ? xs1 : xs0;
        if (LAYER == 1) {
            for (int idx = tid; idx < 32 * NCH; idx += 256) {
                int row = idx / NCH, ch = idx - row * NCH;
                int tok = toks[row * SEQLEN + t];
                cpa16(dbase + row * (KXP * 2) + ch * 16,
                      g_embbf + (size_t)tok * 128 + ch * 8);
            }
        } else {
            for (int idx = tid; idx < 32 * NCH; idx += 256) {
                int row = idx >> 3, ch = idx & 7;
                cpa16(dbase + row * (KXP * 2) + ch * 16,
                      g_h1bf + ((size_t)(b0 + row) * SEQLEN + t) * UNITS + ch * 8);
            }
        }
    };

    // prologue: stage x(0)
    stage_x(0, 0);
    CPA_COMMIT();
    CPA_WAIT0();
    __syncthreads();

    float cst[2][2][2];
    #pragma unroll
    for (int mt = 0; mt < 2; mt++)
        for (int rs = 0; rs < 2; rs++)
            for (int uu = 0; uu < 2; uu++) cst[mt][rs][uu] = 0.f;

    int p = 0;
    for (int t = 0; t < SEQLEN; ++t) {
        // prefetch x(t+1) into the other buffer (overlaps with mma below)
        if (t + 1 < SEQLEN) stage_x((t + 1) & 1, t + 1);
        CPA_COMMIT();

        // acc = bias
        float acc[2][4][4];
        #pragma unroll
        for (int mt = 0; mt < 2; mt++)
            #pragma unroll
            for (int gg = 0; gg < 4; gg++) {
                acc[mt][gg][0] = bx[gg][0]; acc[mt][gg][1] = bx[gg][1];
                acc[mt][gg][2] = bx[gg][0]; acc[mt][gg][3] = bx[gg][1];
            }

        // z += x(t) @ W
        const uint32_t xb = (t & 1) ? xs1 : xs0;
        #pragma unroll
        for (int kt = 0; kt < NKT; kt++) {
            uint32_t a0[4], a1[4];
            ldmx4(a0, xb + a_lane_x + (uint32_t)(kt * 32));
            ldmx4(a1, xb + a_lane_x + (uint32_t)(16 * KXP * 2 + kt * 32));
            #pragma unroll
            for (int gg = 0; gg < 4; gg++) {
                mma16816(acc[0][gg], a0, bw[gg][kt]);
                mma16816(acc[1][gg], a1, bw[gg][kt]);
            }
        }
        // z += h(t-1) @ U
        const uint32_t hb = p ? h1b : h0b;
        #pragma unroll
        for (int kt = 0; kt < 4; kt++) {
            uint32_t a0[4], a1[4];
            ldmx4(a0, hb + a_lane_h + (uint32_t)(kt * 32));
            ldmx4(a1, hb + a_lane_h + (uint32_t)(16 * 144 + kt * 32));
            #pragma unroll
            for (int gg = 0; gg < 4; gg++) {
                mma16816(acc[0][gg], a0, bu[gg][kt]);
                mma16816(acc[1][gg], a1, bu[gg][kt]);
            }
        }

        // gates + state update + h write
        #pragma unroll
        for (int mt = 0; mt < 2; mt++)
            #pragma unroll
            for (int rs = 0; rs < 2; rs++) {
                const int row = mt * 16 + g + rs * 8;
                float hv0, hv1;
                {
                    float zi = acc[mt][0][rs * 2], zf = acc[mt][1][rs * 2];
                    float zg = acc[mt][2][rs * 2], zo = acc[mt][3][rs * 2];
                    float cn = sigf(zf) * cst[mt][rs][0] + sigf(zi) * tanhapx(zg);
                    cst[mt][rs][0] = cn;
                    hv0 = sigf(zo) * tanhapx(cn);
                }
                {
                    float zi = acc[mt][0][rs * 2 + 1], zf = acc[mt][1][rs * 2 + 1];
                    float zg = acc[mt][2][rs * 2 + 1], zo = acc[mt][3][rs * 2 + 1];
                    float cn = sigf(zf) * cst[mt][rs][1] + sigf(zi) * tanhapx(zg);
                    cst[mt][rs][1] = cn;
                    hv1 = sigf(zo) * tanhapx(cn);
                }
                __nv_bfloat162 h2 = __float22bfloat162_rn(make_float2(hv0, hv1));
                *(__nv_bfloat162*)&hsm[p ^ 1][row][wid * 8 + t4 * 2] = h2;
                if (LAYER == 1) {
                    *(__nv_bfloat162*)&g_h1bf[((size_t)(b0 + row) * SEQLEN + t) * UNITS +
                                              wid * 8 + t4 * 2] = h2;
                } else if (t == SEQLEN - 1) {
                    *(float2*)&g_h2[(size_t)(b0 + row) * UNITS + wid * 8 + t4 * 2] =
                        make_float2(hv0, hv1);
                }
            }

        CPA_WAIT0();      // x(t+1) landed
        __syncthreads();  // h(t) + x(t+1) visible to all
        p ^= 1;
    }
}

// ---------------------------------------------------------------------------
// Final dense + sigmoid
// ---------------------------------------------------------------------------
__global__ void __launch_bounds__(128) dense_kernel(
    const float* __restrict__ Wd, const float* __restrict__ bd,
    float* __restrict__ out)
{
    __shared__ float wds[64];
    if (threadIdx.x < 64) wds[threadIdx.x] = Wd[threadIdx.x];
    __syncthreads();
    int b = blockIdx.x * blockDim.x + threadIdx.x;
    float s = bd[0];
    const float* h = &g_h2[b * 64];
    #pragma unroll
    for (int u = 0; u < 64; u++) s += h[u] * wds[u];
    out[b] = 1.0f / (1.0f + __expf(-s));
}

// ---------------------------------------------------------------------------
extern "C" void kernel_launch(void* const* d_in, const int* in_sizes, int n_in,
                              void* d_out, int out_size)
{
    const int*   tokens = (const int*)  d_in[0];
    const float* emb    = (const float*)d_in[1];
    const float* W1     = (const float*)d_in[2];
    const float* U1     = (const float*)d_in[3];
    const float* b1     = (const float*)d_in[4];
    const float* U2     = (const float*)d_in[6];
    const float* W2     = (const float*)d_in[5];
    const float* b2     = (const float*)d_in[7];
    const float* Wd     = (const float*)d_in[8];
    const float* bd     = (const float*)d_in[9];
    float* out = (float*)d_out;

    // one-time bf16 conversions (zero-padded where needed)
    conv_emb_kernel<<<10000 * 128 / 256, 256>>>(emb);
    conv_w1_kernel<<<256 * 128 / 256, 256>>>(W1);
    conv_w2_kernel<<<256 * 64 / 256, 256>>>(W2);

    // layer 1: fused (emb gather + x@W1 + h@U1 recurrence), emits h1 bf16
    lstm_fused<112, 1><<<BATCHN / 32, 256>>>(tokens, U1, b1);
    // layer 2: fused (h1 stream + x@W2 + h@U2 recurrence), keeps last h
    lstm_fused<64, 2><<<BATCHN / 32, 256>>>(nullptr, U2, b2);

    // head
    dense_kernel<<<BATCHN / 128, 128>>>(Wd, bd, out);
}